// round 6
// baseline (speedup 1.0000x reference)
#include <cuda_runtime.h>

#define CHUNK  128
#define MAXW   79
#define MAXN   (MAXW * CHUNK)   // 10112
#define MAXP   1000
#define NBUCK  16384

typedef unsigned long long u64;

// ---- static device scratch (no allocations allowed) ----
__device__ ulonglong2 g_mask[(size_t)MAXN * MAXW];  // suppression bitmask rows (128-bit words)
__device__ ulonglong2 g_diag[MAXN];                 // compact diagonal-block masks
__device__ float4     g_sboxes[MAXN];               // boxes in sorted order
__device__ float      g_sscores[MAXN];              // scores in sorted order
__device__ ulonglong2 g_keep[MAXW];                 // keep bits per 128-chunk
__device__ int        g_prefix[MAXW];               // kept-count prefix per chunk
__device__ int        g_cnt[NBUCK];                 // bucket histogram (self-cleaned)
__device__ int        g_fill[NBUCK];                // bucket fill cursors (self-cleaned)
__device__ int        g_base[NBUCK];                // bucket base (descending order)
__device__ int        g_members[MAXN];              // indices grouped by bucket

__device__ __forceinline__ unsigned bucket_of(float s) {
    int b = (int)(s * 16384.0f);           // monotone for s >= 0
    b = max(0, min(NBUCK - 1, b));
    return (unsigned)b;
}

// ---------------------------------------------------------------------------
// S1: histogram of value buckets (g_cnt starts zero: zero-initialized statics,
// then self-cleaned by k_scanhist each replay)
// ---------------------------------------------------------------------------
__global__ void k_hist(const float* __restrict__ scores, int N) {
    int i = blockIdx.x * blockDim.x + threadIdx.x;
    if (i >= N) return;
    atomicAdd(&g_cnt[bucket_of(scores[i])], 1);
}

// ---------------------------------------------------------------------------
// S2: exclusive scan over buckets in DESCENDING bucket order, COALESCED.
// Also zeroes g_cnt (for next replay's k_hist) and g_fill (for this replay's
// k_fill) as it goes.
// ---------------------------------------------------------------------------
__global__ void k_scanhist() {
    __shared__ int wsum[32];
    int t = threadIdx.x;
    int lane = t & 31, wid = t >> 5;
    int cbase = 0;

    for (int k = 0; k < NBUCK / 1024; k++) {
        int b = NBUCK - 1 - (k * 1024 + t);   // descending, coalesced
        int v = g_cnt[b];
        g_cnt[b]  = 0;   // self-clean for next replay
        g_fill[b] = 0;   // reset cursors for this replay
        int x = v;
        #pragma unroll
        for (int off = 1; off < 32; off <<= 1) {
            int y = __shfl_up_sync(~0u, x, off);
            if (lane >= off) x += y;
        }
        if (lane == 31) wsum[wid] = x;
        __syncthreads();
        if (wid == 0) {
            int s = wsum[lane];
            #pragma unroll
            for (int off = 1; off < 32; off <<= 1) {
                int y = __shfl_up_sync(~0u, s, off);
                if (lane >= off) s += y;
            }
            wsum[lane] = s;
        }
        __syncthreads();
        int excl = cbase + (x - v) + (wid ? wsum[wid - 1] : 0);
        g_base[b] = excl;
        cbase += wsum[31];
        __syncthreads();
    }
}

// ---------------------------------------------------------------------------
// S3: deposit element indices into their bucket's slot range
// ---------------------------------------------------------------------------
__global__ void k_fill(const float* __restrict__ scores, int N) {
    int i = blockIdx.x * blockDim.x + threadIdx.x;
    if (i >= N) return;
    unsigned b = bucket_of(scores[i]);
    int slot = g_base[b] + atomicAdd(&g_fill[b], 1);
    g_members[slot] = i;
}

// ---------------------------------------------------------------------------
// S4: exact stable rank within bucket + scatter. Bucket count recovered as a
// base-difference (g_cnt has been zeroed by k_scanhist).
// ---------------------------------------------------------------------------
__global__ void k_place(const float4* __restrict__ boxes,
                        const float* __restrict__ scores, int N) {
    int i = blockIdx.x * blockDim.x + threadIdx.x;
    if (i >= N) return;
    float si = scores[i];
    unsigned b = bucket_of(si);
    int base = g_base[b];
    int cb   = ((b == 0) ? N : g_base[b - 1]) - base;
    int r = base;
    for (int t = 0; t < cb; t++) {
        int j = g_members[base + t];
        if (j == i) continue;
        float sj = scores[j];
        r += (sj > si) || (sj == si && j < i);
    }
    g_sboxes[r]  = boxes[i];
    g_sscores[r] = si;
}

// ---------------------------------------------------------------------------
// K2: pairwise IoU suppression bitmask, 128x128 tiles, upper triangle.
// suppress <=> IoU > 0.5 <=> 3*inter > areaR + areaC  (division-free).
// Padding boxes are all-zero -> inter=0, sum=0 -> never suppress.
// ---------------------------------------------------------------------------
__global__ void k_mask(int N, int W) {
    int cb = blockIdx.x, rb = blockIdx.y;
    if (cb < rb) return;
    __shared__ float4 cbox[CHUNK];
    __shared__ float  carea[CHUNK];
    int t  = threadIdx.x;
    int cg = cb * CHUNK + t;
    float4 cv = (cg < N) ? g_sboxes[cg] : make_float4(0.f, 0.f, 0.f, 0.f);
    cbox[t]  = cv;
    carea[t] = (cv.z - cv.x) * (cv.w - cv.y);
    __syncthreads();

    int rg = rb * CHUNK + t;
    if (rg >= N) return;
    float4 r = g_sboxes[rg];
    float ra = (r.z - r.x) * (r.w - r.y);

    u64 m0 = 0, m1 = 0;
    if (cb > rb) {
        #pragma unroll 16
        for (int j = 0; j < 64; j++) {
            float4 c = cbox[j];
            float ix1 = fmaxf(r.x, c.x), iy1 = fmaxf(r.y, c.y);
            float ix2 = fminf(r.z, c.z), iy2 = fminf(r.w, c.w);
            float inter = fmaxf(ix2 - ix1, 0.0f) * fmaxf(iy2 - iy1, 0.0f);
            if (3.0f * inter > ra + carea[j]) m0 |= 1ull << j;
        }
        #pragma unroll 16
        for (int j = 64; j < 128; j++) {
            float4 c = cbox[j];
            float ix1 = fmaxf(r.x, c.x), iy1 = fmaxf(r.y, c.y);
            float ix2 = fminf(r.z, c.z), iy2 = fminf(r.w, c.w);
            float inter = fmaxf(ix2 - ix1, 0.0f) * fmaxf(iy2 - iy1, 0.0f);
            if (3.0f * inter > ra + carea[j]) m1 |= 1ull << (j - 64);
        }
    } else {
        // diagonal tile: only suppress later (lower-score) boxes j > t
        #pragma unroll 16
        for (int j = 0; j < 128; j++) {
            if (j <= t) continue;
            float4 c = cbox[j];
            float ix1 = fmaxf(r.x, c.x), iy1 = fmaxf(r.y, c.y);
            float ix2 = fminf(r.z, c.z), iy2 = fminf(r.w, c.w);
            float inter = fmaxf(ix2 - ix1, 0.0f) * fmaxf(iy2 - iy1, 0.0f);
            if (3.0f * inter > ra + carea[j]) {
                if (j < 64) m0 |= 1ull << j; else m1 |= 1ull << (j - 64);
            }
        }
        g_diag[rg] = make_ulonglong2(m0, m1);
    }
    g_mask[(size_t)rg * W + cb] = make_ulonglong2(m0, m1);
}

// ---------------------------------------------------------------------------
// K3: pipelined greedy scan over 128-wide chunks with early termination.
// Thread 0 gathers word w=c+1 then runs phase A for chunk c+1 in the same
// round; threads 1..W-2-c gather their words; threads 128..255 prefetch the
// next diag tile. One barrier per round.
// ---------------------------------------------------------------------------
__global__ void k_scan(int N, int W) {
    __shared__ ulonglong2 removed[MAXW];
    __shared__ ulonglong2 diagbuf[2][CHUNK];
    __shared__ unsigned char klist[2][CHUNK];
    __shared__ int s_nk[2];
    __shared__ int s_stop, s_cstop;
    int tid = threadIdx.x;

    for (int w = tid; w < W; w += blockDim.x) removed[w] = make_ulonglong2(0ull, 0ull);
    if (tid < CHUNK) {
        diagbuf[0][tid] = (tid < N) ? g_diag[tid] : make_ulonglong2(0ull, 0ull);
        int g1 = CHUNK + tid;
        diagbuf[1][tid] = (W > 1 && g1 < N) ? g_diag[g1] : make_ulonglong2(0ull, 0ull);
    }
    if (tid == 0) { s_stop = 0; s_cstop = W; }
    __syncthreads();

    int total = 0;  // thread 0 only

    // phase A for chunk 0
    if (tid == 0) {
        const ulonglong2* d = diagbuf[0];
        int valid = min(N, CHUNK);
        u64 v0 = (valid >= 64) ? ~0ull : ((1ull << valid) - 1ull);
        int v2 = valid - 64;
        u64 v1 = (v2 >= 64) ? ~0ull : ((v2 <= 0) ? 0ull : ((1ull << v2) - 1ull));
        u64 p0 = v0, p1 = v1, k0 = 0ull, k1 = 0ull;
        int n = 0;
        while (p0 | p1) {
            int i = p0 ? (__ffsll((long long)p0) - 1) : (64 + __ffsll((long long)p1) - 1);
            klist[0][n++] = (unsigned char)i;
            ulonglong2 dd = d[i];
            if (i < 64) { k0 |= 1ull << i; p0 &= ~(1ull << i); }
            else        { k1 |= 1ull << (i - 64); p1 &= ~(1ull << (i - 64)); }
            p0 &= ~dd.x; p1 &= ~dd.y;
        }
        g_keep[0] = make_ulonglong2(k0, k1);
        g_prefix[0] = 0;
        total = __popcll(k0) + __popcll(k1);
        s_nk[0] = n;
        if (total >= MAXP) { s_stop = 1; s_cstop = 1; }
    }
    __syncthreads();

    for (int c = 0; c + 1 < W; c++) {
        if (s_stop) break;
        int pb = c & 1;
        int nk = s_nk[pb];
        const unsigned char* kl = klist[pb];
        int w = c + 1 + tid;

        ulonglong2 acc = make_ulonglong2(0ull, 0ull);
        if (w < W) {
            acc = removed[w];
            const ulonglong2* mp = g_mask + w;
            size_t cb128 = (size_t)c * CHUNK;
            for (int t = 0; t < nk; t += 8) {
                u64 ax = 0ull, ay = 0ull;
                #pragma unroll
                for (int u = 0; u < 8; u++) {
                    if (t + u < nk) {
                        ulonglong2 v = mp[(cb128 + kl[t + u]) * W];
                        ax |= v.x; ay |= v.y;
                    }
                }
                acc.x |= ax; acc.y |= ay;
            }
        }

        if (tid == 0) {
            // phase A for chunk c+1; rem = freshly gathered acc
            int cc = c + 1;
            const ulonglong2* d = diagbuf[cc & 1];
            int valid = N - cc * CHUNK;
            u64 v0 = (valid >= 64) ? ~0ull : ((valid <= 0) ? 0ull : ((1ull << valid) - 1ull));
            int v2 = valid - 64;
            u64 v1 = (v2 >= 64) ? ~0ull : ((v2 <= 0) ? 0ull : ((1ull << v2) - 1ull));
            u64 p0 = ~acc.x & v0, p1 = ~acc.y & v1;
            u64 k0 = 0ull, k1 = 0ull;
            int n = 0;
            while (p0 | p1) {
                int i = p0 ? (__ffsll((long long)p0) - 1) : (64 + __ffsll((long long)p1) - 1);
                klist[cc & 1][n++] = (unsigned char)i;
                ulonglong2 dd = d[i];
                if (i < 64) { k0 |= 1ull << i; p0 &= ~(1ull << i); }
                else        { k1 |= 1ull << (i - 64); p1 &= ~(1ull << (i - 64)); }
                p0 &= ~dd.x; p1 &= ~dd.y;
            }
            g_keep[cc] = make_ulonglong2(k0, k1);
            g_prefix[cc] = total;
            total += __popcll(k0) + __popcll(k1);
            s_nk[cc & 1] = n;
            if (total >= MAXP) { s_stop = 1; s_cstop = cc + 1; }
        } else if (w < W) {
            removed[w] = acc;
        }

        // prefetch diag tile for chunk c+2 (tid>=128 never gathers: W<=79)
        if (tid >= 128 && c + 2 < W) {
            int g = (c + 2) * CHUNK + (tid - 128);
            diagbuf[(c + 2) & 1][tid - 128] =
                (g < N) ? g_diag[g] : make_ulonglong2(0ull, 0ull);
        }
        __syncthreads();
    }

    int cstop = s_cstop;
    for (int c2 = cstop + tid; c2 < W; c2 += blockDim.x)
        g_keep[c2] = make_ulonglong2(0ull, 0ull);
}

// ---------------------------------------------------------------------------
// K4: apply MAX_PROPOSALS cutoff and emit outputs:
//   out[0 : 4N) boxes | out[4N : 5N) scores | out[5N : 6N) keep as 0/1
// ---------------------------------------------------------------------------
__global__ void k_out(float* __restrict__ out, int N) {
    int p = blockIdx.x * blockDim.x + threadIdx.x;
    if (p >= N) return;
    int c = p >> 7, i = p & 127;
    ulonglong2 kw = g_keep[c];
    bool kept;
    int below;
    if (i < 64) {
        kept  = (kw.x >> i) & 1ull;
        below = __popcll(kw.x & ((1ull << i) - 1ull));
    } else {
        int ii = i - 64;
        kept  = (kw.y >> ii) & 1ull;
        below = __popcll(kw.x) + __popcll(kw.y & ((1ull << ii) - 1ull));
    }
    int r = g_prefix[c] + below;
    bool fin = kept && (r < MAXP);

    float4 b = fin ? g_sboxes[p] : make_float4(0.f, 0.f, 0.f, 0.f);
    ((float4*)out)[p] = b;
    out[4 * N + p] = fin ? g_sscores[p] : 0.0f;
    out[5 * N + p] = fin ? 1.0f : 0.0f;
}

// ---------------------------------------------------------------------------
extern "C" void kernel_launch(void* const* d_in, const int* in_sizes, int n_in,
                              void* d_out, int out_size) {
    const float4* boxes  = (const float4*)d_in[0];
    const float*  scores = (const float*)d_in[1];
    int N = in_sizes[1];
    int W = (N + CHUNK - 1) / CHUNK;

    k_hist<<<(N + 255) / 256, 256>>>(scores, N);
    k_scanhist<<<1, 1024>>>();
    k_fill<<<(N + 255) / 256, 256>>>(scores, N);
    k_place<<<(N + 255) / 256, 256>>>(boxes, scores, N);

    dim3 g2(W, W);
    k_mask<<<g2, CHUNK>>>(N, W);

    k_scan<<<1, 256>>>(N, W);

    k_out<<<(N + 255) / 256, 256>>>((float*)d_out, N);
}